// round 14
// baseline (speedup 1.0000x reference)
#include <cuda_runtime.h>
#include <cuda_fp16.h>
#include <stdint.h>
#include <math.h>

// ---------------------------------------------------------------------------
// BitNet-b1.58 FFN. compute_103 base target (sm_80-era mma.sync path).
// R5: 494.0us. R12 profile of gemm1: tensor=51%, issue=27%, occ=24%,
// regs=124/128 cap -> warps stall on LDSM->HMMA deps, no reg headroom to
// pipeline. R13: 128 thr / 64x64 warp tiles (reg cap 255) + explicit
// double-buffered fragments across ks -> fill issue bubbles.
// ---------------------------------------------------------------------------

#define EMB   1024
#define FF    4096
#define MTOK  8192
#define WELEM (FF * EMB)

__device__ __align__(256) __half  g_xh[MTOK * EMB];
__device__ __align__(256) __half  g_w1h[FF * EMB];
__device__ __align__(256) __half  g_w2h[EMB * FF];
__device__ __align__(256) __half  g_hh[(size_t)MTOK * FF];
__device__ double                 g_partials[2][1024];
__device__ float                  g_scales[2];

// ---------------------------------------------------------------------------
__device__ __forceinline__ uint32_t smem_u32(const void* p) {
    uint32_t a;
    asm("{ .reg .u64 t; cvta.to.shared.u64 t, %1; cvt.u32.u64 %0, t; }" : "=r"(a) : "l"(p));
    return a;
}
__device__ __forceinline__ void cp_async16(uint32_t dst, const void* src) {
    asm volatile("cp.async.cg.shared.global [%0], [%1], 16;" :: "r"(dst), "l"(src));
}
__device__ __forceinline__ void cp_commit() {
    asm volatile("cp.async.commit_group;");
}
template <int N>
__device__ __forceinline__ void cp_wait() {
    asm volatile("cp.async.wait_group %0;" :: "n"(N));
}
__device__ __forceinline__ void ldmatrix_x4(uint32_t* r, uint32_t addr) {
    asm volatile("ldmatrix.sync.aligned.m8n8.x4.shared.b16 {%0,%1,%2,%3}, [%4];"
                 : "=r"(r[0]), "=r"(r[1]), "=r"(r[2]), "=r"(r[3]) : "r"(addr));
}
__device__ __forceinline__ void mma16816(float* c, const uint32_t* a, const uint32_t* b) {
    asm volatile("mma.sync.aligned.m16n8k16.row.col.f32.f16.f16.f32 "
                 "{%0,%1,%2,%3}, {%4,%5,%6,%7}, {%8,%9}, {%0,%1,%2,%3};"
                 : "+f"(c[0]), "+f"(c[1]), "+f"(c[2]), "+f"(c[3])
                 : "r"(a[0]), "r"(a[1]), "r"(a[2]), "r"(a[3]), "r"(b[0]), "r"(b[1]));
}

// ---------------------------------------------------------------------------
// Prep (unchanged from R7; 5 launches keeps gemm1 at ncu capture idx 3)
// ---------------------------------------------------------------------------
__global__ void reduce_abs2(const float4* __restrict__ w1, const float4* __restrict__ w2) {
    __shared__ double sd[256];
    int which = blockIdx.x >> 10;
    const float4* w = which ? w2 : w1;
    int base = (blockIdx.x & 1023) * 1024;
    double s = 0.0;
#pragma unroll
    for (int i = 0; i < 4; i++) {
        float4 v = w[base + threadIdx.x + i * 256];
        s += (double)fabsf(v.x) + (double)fabsf(v.y) + (double)fabsf(v.z) + (double)fabsf(v.w);
    }
    sd[threadIdx.x] = s;
    __syncthreads();
    for (int st = 128; st > 0; st >>= 1) {
        if (threadIdx.x < st) sd[threadIdx.x] += sd[threadIdx.x + st];
        __syncthreads();
    }
    if (threadIdx.x == 0) g_partials[which][blockIdx.x & 1023] = sd[0];
}

__global__ void finalize_scales() {
    __shared__ double sd[1024];
    int t = threadIdx.x;
    sd[t] = g_partials[blockIdx.x][t];
    __syncthreads();
    for (int s = 512; s > 0; s >>= 1) {
        if (t < s) sd[t] += sd[t + s];
        __syncthreads();
    }
    if (t == 0) {
        float mean = (float)(sd[0] / (double)WELEM);
        g_scales[blockIdx.x] = fmaxf(mean, 1e-8f);
    }
}

__global__ void prep_fused(const float4* __restrict__ w1, const float4* __restrict__ w2,
                           const float4* __restrict__ x) {
    int b = blockIdx.x;
    if (b < 8192) {
        int which = b >> 12;
        const float4* src = which ? w2 : w1;
        __half* dst = which ? g_w2h : g_w1h;
        float sc = g_scales[which];
        int i = (b & 4095) * 256 + threadIdx.x;
        float4 v = src[i];
        float q0 = fminf(fmaxf(rintf(__fdiv_rn(v.x, sc)), -1.f), 1.f);
        float q1 = fminf(fmaxf(rintf(__fdiv_rn(v.y, sc)), -1.f), 1.f);
        float q2 = fminf(fmaxf(rintf(__fdiv_rn(v.z, sc)), -1.f), 1.f);
        float q3 = fminf(fmaxf(rintf(__fdiv_rn(v.w, sc)), -1.f), 1.f);
        __half2 h0 = __floats2half2_rn(q0, q1);
        __half2 h1 = __floats2half2_rn(q2, q3);
        uint2 pk = make_uint2(*(uint32_t*)&h0, *(uint32_t*)&h1);
        *(uint2*)(dst + (size_t)i * 4) = pk;
    } else {
        int i = (b - 8192) * 256 + threadIdx.x;
        float4 v = x[i];
        __half2 h0 = __floats2half2_rn(v.x, v.y);
        __half2 h1 = __floats2half2_rn(v.z, v.w);
        uint2 pk = make_uint2(*(uint32_t*)&h0, *(uint32_t*)&h1);
        *(uint2*)(g_xh + (size_t)i * 4) = pk;
    }
}

// ---------------------------------------------------------------------------
// Multistage fp16 GEMM: CTA 128x128, 128 threads, 4 warps 2x2 (64x64 tiles),
// K-chunk 64, 3 stages cp.async, single barrier/chunk, pitch 144B.
// NEW: ks-level fragment double-buffering (load ks+1 while computing ks).
// ---------------------------------------------------------------------------
#define STG 18432                   // 128 rows * 144B per matrix per stage
#define SMEM_DYN (3 * 2 * STG)      // 110592 B; 2 CTAs/SM

template <int EPI>
__global__ __launch_bounds__(128, 2) void gemm_fp16(const float* __restrict__ bias,
                                                    float* __restrict__ outf) {
    constexpr int N_ = (EPI == 1) ? FF : EMB;
    constexpr int K_ = (EPI == 1) ? EMB : FF;
    constexpr int KT = K_ / 64;
    const __half* __restrict__ A = (EPI == 1) ? g_xh : g_hh;
    const __half* __restrict__ B = (EPI == 1) ? g_w1h : g_w2h;

    extern __shared__ char smem_raw[];
    uint32_t sb = smem_u32(smem_raw);
    const uint32_t As = sb, Bs = sb + 3 * STG;

    int tid = threadIdx.x, lane = tid & 31, wid = tid >> 5;
    int wm = wid & 1, wn = wid >> 1;            // 2 x 2 warps, 64x64 tiles

    // grouped rasterization for L2 reuse
    constexpr int TN = N_ / 128, TMt = MTOK / 128, GM = 16;
    int bid = blockIdx.x;
    int grp = bid / (GM * TN), rem = bid % (GM * TN);
    int gsz = (GM < TMt - grp * GM) ? GM : (TMt - grp * GM);
    int tm = grp * GM + rem % gsz, tn = rem / gsz;

    const __half* Ag = A + (size_t)tm * 128 * K_;
    const __half* Bg = B + (size_t)tn * 128 * K_;

    float acc[4][8][4];
#pragma unroll
    for (int i = 0; i < 4; i++)
#pragma unroll
        for (int j = 0; j < 8; j++)
#pragma unroll
            for (int k = 0; k < 4; k++) acc[i][j][k] = 0.f;

    // stage loader: 128 rows x 8 chunks(16B) per matrix; 8+8 cp.async/thread
    int r0 = tid >> 3, c0 = tid & 7;            // r0: 0..15
    auto load_stage = [&](int kt, int s) {
        uint32_t ab = As + (uint32_t)s * STG;
        uint32_t bb = Bs + (uint32_t)s * STG;
        const __half* ga = Ag + kt * 64 + c0 * 8;
        const __half* gb = Bg + kt * 64 + c0 * 8;
#pragma unroll
        for (int i = 0; i < 8; i++) {
            int row = r0 + i * 16;
            cp_async16(ab + row * 144 + c0 * 16, ga + (size_t)row * K_);
            cp_async16(bb + row * 144 + c0 * 16, gb + (size_t)row * K_);
        }
    };

    load_stage(0, 0); cp_commit();
    load_stage(1, 1); cp_commit();

    // ldmatrix address components
    int a_row = wm * 64 + (lane & 15);                           // + mi*16
    int a_c   = (lane >> 4);                                     // + ks*2
    int b_row = wn * 64 + (lane & 7) + ((lane & 16) ? 8 : 0);    // + nj*16
    int b_c   = ((lane >> 3) & 1);                               // + ks*2

    uint32_t af[2][4][4], bf[2][4][4];          // double-buffered fragments

    int sr = 0, sw = 2;
    for (int kt = 0; kt < KT; kt++) {
        cp_wait<1>();
        __syncthreads();          // orders reads of sr AND overwrite of sw
        if (kt + 2 < KT) load_stage(kt + 2, sw);
        cp_commit();

        uint32_t ab = As + (uint32_t)sr * STG;
        uint32_t bb = Bs + (uint32_t)sr * STG;

        // prologue: fragments for ks=0 into buffer 0
#pragma unroll
        for (int mi = 0; mi < 4; mi++)
            ldmatrix_x4(af[0][mi], ab + (a_row + mi * 16) * 144 + a_c * 16);
#pragma unroll
        for (int nj = 0; nj < 4; nj++)
            ldmatrix_x4(bf[0][nj], bb + (b_row + nj * 16) * 144 + b_c * 16);

#pragma unroll
        for (int ks = 0; ks < 4; ks++) {
            int cur = ks & 1, nxt = cur ^ 1;
            if (ks < 3) {           // prefetch ks+1 fragments while computing ks
#pragma unroll
                for (int mi = 0; mi < 4; mi++)
                    ldmatrix_x4(af[nxt][mi],
                                ab + (a_row + mi * 16) * 144 + (a_c + (ks + 1) * 2) * 16);
#pragma unroll
                for (int nj = 0; nj < 4; nj++)
                    ldmatrix_x4(bf[nxt][nj],
                                bb + (b_row + nj * 16) * 144 + (b_c + (ks + 1) * 2) * 16);
            }
#pragma unroll
            for (int mi = 0; mi < 4; mi++)
#pragma unroll
                for (int n8 = 0; n8 < 8; n8++)
                    mma16816(acc[mi][n8], af[cur][mi], &bf[cur][n8 >> 1][(n8 & 1) * 2]);
        }
        sr = (sr + 1 == 3) ? 0 : sr + 1;
        sw = (sw + 1 == 3) ? 0 : sw + 1;
    }

    // Epilogue: +bias (and exact-erf GELU for EPI==1), direct vector stores
    int erow = tm * 128 + wm * 64 + (lane >> 2);
    int ecol = tn * 128 + wn * 64 + 2 * (lane & 3);
#pragma unroll
    for (int mi = 0; mi < 4; mi++) {
#pragma unroll
        for (int n8 = 0; n8 < 8; n8++) {
            int r = erow + mi * 16;
            int c = ecol + n8 * 8;
            float bv0 = __ldg(bias + c), bv1 = __ldg(bias + c + 1);
            float v0 = acc[mi][n8][0] + bv0, v1 = acc[mi][n8][1] + bv1;
            float v2 = acc[mi][n8][2] + bv0, v3 = acc[mi][n8][3] + bv1;
            if (EPI == 1) {
                const float is2 = 0.70710678118654752f;
                v0 = 0.5f * v0 * (1.0f + erff(v0 * is2));
                v1 = 0.5f * v1 * (1.0f + erff(v1 * is2));
                v2 = 0.5f * v2 * (1.0f + erff(v2 * is2));
                v3 = 0.5f * v3 * (1.0f + erff(v3 * is2));
                __half2* p0 = (__half2*)(g_hh + (size_t)r * N_ + c);
                __half2* p1 = (__half2*)(g_hh + (size_t)(r + 8) * N_ + c);
                *p0 = __floats2half2_rn(v0, v1);
                *p1 = __floats2half2_rn(v2, v3);
            } else {
                float2* p0 = (float2*)(outf + (size_t)r * N_ + c);
                float2* p1 = (float2*)(outf + (size_t)(r + 8) * N_ + c);
                *p0 = make_float2(v0, v1);
                *p1 = make_float2(v2, v3);
            }
        }
    }
}

// ---------------------------------------------------------------------------
extern "C" void kernel_launch(void* const* d_in, const int* in_sizes, int n_in,
                              void* d_out, int out_size) {
    (void)in_sizes; (void)n_in; (void)out_size;
    const float* x  = (const float*)d_in[0];
    const float* W1 = (const float*)d_in[1];
    const float* b1 = (const float*)d_in[2];
    const float* W2 = (const float*)d_in[3];
    const float* b2 = (const float*)d_in[4];
    float* out = (float*)d_out;

    cudaFuncSetAttribute(gemm_fp16<1>, cudaFuncAttributeMaxDynamicSharedMemorySize, SMEM_DYN);
    cudaFuncSetAttribute(gemm_fp16<2>, cudaFuncAttributeMaxDynamicSharedMemorySize, SMEM_DYN);

    // Launch indices: 0 reduce, 1 finalize, 2 prep_fused, 3 gemm1 (<- ncu), 4 gemm2
    reduce_abs2<<<2048, 256>>>((const float4*)W1, (const float4*)W2);
    finalize_scales<<<2, 1024>>>();
    prep_fused<<<16384, 256>>>((const float4*)W1, (const float4*)W2, (const float4*)x);
    gemm_fp16<1><<<(MTOK / 128) * (FF / 128), 128, SMEM_DYN>>>(b1, nullptr);
    gemm_fp16<2><<<(MTOK / 128) * (EMB / 128), 128, SMEM_DYN>>>(b2, out);
}

// round 15
// speedup vs baseline: 1.0527x; 1.0527x over previous
#include <cuda_runtime.h>
#include <cuda_fp16.h>
#include <stdint.h>
#include <math.h>

// ---------------------------------------------------------------------------
// BitNet-b1.58 FFN. compute_103 base target (sm_80-era mma.sync path).
// R5 494us. R12: 64x32/16warps unpip -> tensor 51%. R13: 64x64/8warps
// pipelined -> tensor 50%. Both ~50% => either legacy-HMMA ceiling (rt=8)
// or insufficient (warps x low-smem-traffic) product. R14 Config X tests the
// missing cell: 64x64 tiles (smem cap 68%) + 3 CTAs/SM (3 warps/SMSP) via
// 2-stage smem, single-buffered frags, reg cap 170.
// ---------------------------------------------------------------------------

#define EMB   1024
#define FF    4096
#define MTOK  8192
#define WELEM (FF * EMB)

__device__ __align__(256) __half  g_xh[MTOK * EMB];
__device__ __align__(256) __half  g_w1h[FF * EMB];
__device__ __align__(256) __half  g_w2h[EMB * FF];
__device__ __align__(256) __half  g_hh[(size_t)MTOK * FF];
__device__ double                 g_partials[2][1024];
__device__ float                  g_scales[2];

// ---------------------------------------------------------------------------
__device__ __forceinline__ uint32_t smem_u32(const void* p) {
    uint32_t a;
    asm("{ .reg .u64 t; cvta.to.shared.u64 t, %1; cvt.u32.u64 %0, t; }" : "=r"(a) : "l"(p));
    return a;
}
__device__ __forceinline__ void cp_async16(uint32_t dst, const void* src) {
    asm volatile("cp.async.cg.shared.global [%0], [%1], 16;" :: "r"(dst), "l"(src));
}
__device__ __forceinline__ void cp_commit() {
    asm volatile("cp.async.commit_group;");
}
template <int N>
__device__ __forceinline__ void cp_wait() {
    asm volatile("cp.async.wait_group %0;" :: "n"(N));
}
__device__ __forceinline__ void ldmatrix_x4(uint32_t* r, uint32_t addr) {
    asm volatile("ldmatrix.sync.aligned.m8n8.x4.shared.b16 {%0,%1,%2,%3}, [%4];"
                 : "=r"(r[0]), "=r"(r[1]), "=r"(r[2]), "=r"(r[3]) : "r"(addr));
}
__device__ __forceinline__ void mma16816(float* c, const uint32_t* a, const uint32_t* b) {
    asm volatile("mma.sync.aligned.m16n8k16.row.col.f32.f16.f16.f32 "
                 "{%0,%1,%2,%3}, {%4,%5,%6,%7}, {%8,%9}, {%0,%1,%2,%3};"
                 : "+f"(c[0]), "+f"(c[1]), "+f"(c[2]), "+f"(c[3])
                 : "r"(a[0]), "r"(a[1]), "r"(a[2]), "r"(a[3]), "r"(b[0]), "r"(b[1]));
}

// ---------------------------------------------------------------------------
// Prep (unchanged; 5 launches keeps gemm1 at ncu capture idx 3)
// ---------------------------------------------------------------------------
__global__ void reduce_abs2(const float4* __restrict__ w1, const float4* __restrict__ w2) {
    __shared__ double sd[256];
    int which = blockIdx.x >> 10;
    const float4* w = which ? w2 : w1;
    int base = (blockIdx.x & 1023) * 1024;
    double s = 0.0;
#pragma unroll
    for (int i = 0; i < 4; i++) {
        float4 v = w[base + threadIdx.x + i * 256];
        s += (double)fabsf(v.x) + (double)fabsf(v.y) + (double)fabsf(v.z) + (double)fabsf(v.w);
    }
    sd[threadIdx.x] = s;
    __syncthreads();
    for (int st = 128; st > 0; st >>= 1) {
        if (threadIdx.x < st) sd[threadIdx.x] += sd[threadIdx.x + st];
        __syncthreads();
    }
    if (threadIdx.x == 0) g_partials[which][blockIdx.x & 1023] = sd[0];
}

__global__ void finalize_scales() {
    __shared__ double sd[1024];
    int t = threadIdx.x;
    sd[t] = g_partials[blockIdx.x][t];
    __syncthreads();
    for (int s = 512; s > 0; s >>= 1) {
        if (t < s) sd[t] += sd[t + s];
        __syncthreads();
    }
    if (t == 0) {
        float mean = (float)(sd[0] / (double)WELEM);
        g_scales[blockIdx.x] = fmaxf(mean, 1e-8f);
    }
}

__global__ void prep_fused(const float4* __restrict__ w1, const float4* __restrict__ w2,
                           const float4* __restrict__ x) {
    int b = blockIdx.x;
    if (b < 8192) {
        int which = b >> 12;
        const float4* src = which ? w2 : w1;
        __half* dst = which ? g_w2h : g_w1h;
        float sc = g_scales[which];
        int i = (b & 4095) * 256 + threadIdx.x;
        float4 v = src[i];
        float q0 = fminf(fmaxf(rintf(__fdiv_rn(v.x, sc)), -1.f), 1.f);
        float q1 = fminf(fmaxf(rintf(__fdiv_rn(v.y, sc)), -1.f), 1.f);
        float q2 = fminf(fmaxf(rintf(__fdiv_rn(v.z, sc)), -1.f), 1.f);
        float q3 = fminf(fmaxf(rintf(__fdiv_rn(v.w, sc)), -1.f), 1.f);
        __half2 h0 = __floats2half2_rn(q0, q1);
        __half2 h1 = __floats2half2_rn(q2, q3);
        uint2 pk = make_uint2(*(uint32_t*)&h0, *(uint32_t*)&h1);
        *(uint2*)(dst + (size_t)i * 4) = pk;
    } else {
        int i = (b - 8192) * 256 + threadIdx.x;
        float4 v = x[i];
        __half2 h0 = __floats2half2_rn(v.x, v.y);
        __half2 h1 = __floats2half2_rn(v.z, v.w);
        uint2 pk = make_uint2(*(uint32_t*)&h0, *(uint32_t*)&h1);
        *(uint2*)(g_xh + (size_t)i * 4) = pk;
    }
}

// ---------------------------------------------------------------------------
// fp16 GEMM Config X: CTA 128x128, 128 thr, 4 warps 2x2 (64x64 tiles),
// K-chunk 64, TWO smem stages (73.7KB) -> 3 CTAs/SM, single-buffered frags,
// reg cap 170 via __launch_bounds__(128,3). Two barriers per chunk (2-stage
// write/read hazard).
// ---------------------------------------------------------------------------
#define STG 18432                   // 128 rows * 144B per matrix per stage
#define SMEM_DYN (2 * 2 * STG)      // 73728 B; 3 CTAs/SM = 221KB

template <int EPI>
__global__ __launch_bounds__(128, 3) void gemm_fp16(const float* __restrict__ bias,
                                                    float* __restrict__ outf) {
    constexpr int N_ = (EPI == 1) ? FF : EMB;
    constexpr int K_ = (EPI == 1) ? EMB : FF;
    constexpr int KT = K_ / 64;
    const __half* __restrict__ A = (EPI == 1) ? g_xh : g_hh;
    const __half* __restrict__ B = (EPI == 1) ? g_w1h : g_w2h;

    extern __shared__ char smem_raw[];
    uint32_t sb = smem_u32(smem_raw);
    const uint32_t As = sb, Bs = sb + 2 * STG;

    int tid = threadIdx.x, lane = tid & 31, wid = tid >> 5;
    int wm = wid & 1, wn = wid >> 1;            // 2 x 2 warps, 64x64 tiles

    // grouped rasterization for L2 reuse
    constexpr int TN = N_ / 128, TMt = MTOK / 128, GM = 16;
    int bid = blockIdx.x;
    int grp = bid / (GM * TN), rem = bid % (GM * TN);
    int gsz = (GM < TMt - grp * GM) ? GM : (TMt - grp * GM);
    int tm = grp * GM + rem % gsz, tn = rem / gsz;

    const __half* Ag = A + (size_t)tm * 128 * K_;
    const __half* Bg = B + (size_t)tn * 128 * K_;

    float acc[4][8][4];
#pragma unroll
    for (int i = 0; i < 4; i++)
#pragma unroll
        for (int j = 0; j < 8; j++)
#pragma unroll
            for (int k = 0; k < 4; k++) acc[i][j][k] = 0.f;

    // stage loader: 128 rows x 8 chunks(16B) per matrix; 8+8 cp.async/thread
    int r0 = tid >> 3, c0 = tid & 7;            // r0: 0..15
    auto load_stage = [&](int kt, int s) {
        uint32_t ab = As + (uint32_t)s * STG;
        uint32_t bb = Bs + (uint32_t)s * STG;
        const __half* ga = Ag + kt * 64 + c0 * 8;
        const __half* gb = Bg + kt * 64 + c0 * 8;
#pragma unroll
        for (int i = 0; i < 8; i++) {
            int row = r0 + i * 16;
            cp_async16(ab + row * 144 + c0 * 16, ga + (size_t)row * K_);
            cp_async16(bb + row * 144 + c0 * 16, gb + (size_t)row * K_);
        }
    };

    load_stage(0, 0); cp_commit();

    // ldmatrix address components
    int a_row = wm * 64 + (lane & 15);                           // + mi*16
    int a_c   = (lane >> 4);                                     // + ks*2
    int b_row = wn * 64 + (lane & 7) + ((lane & 16) ? 8 : 0);    // + nj*16
    int b_c   = ((lane >> 3) & 1);                               // + ks*2

    for (int kt = 0; kt < KT; kt++) {
        if (kt + 1 < KT) {
            load_stage(kt + 1, (kt + 1) & 1);
            cp_commit();
            cp_wait<1>();          // stage kt arrived (kt+1 in flight)
        } else {
            cp_wait<0>();
        }
        __syncthreads();           // all warps see stage kt&1

        uint32_t ab = As + (uint32_t)(kt & 1) * STG;
        uint32_t bb = Bs + (uint32_t)(kt & 1) * STG;
#pragma unroll
        for (int ks = 0; ks < 4; ks++) {
            uint32_t af[4][4], bf[4][4];
#pragma unroll
            for (int mi = 0; mi < 4; mi++)
                ldmatrix_x4(af[mi], ab + (a_row + mi * 16) * 144 + (a_c + ks * 2) * 16);
#pragma unroll
            for (int nj = 0; nj < 4; nj++)
                ldmatrix_x4(bf[nj], bb + (b_row + nj * 16) * 144 + (b_c + ks * 2) * 16);
#pragma unroll
            for (int mi = 0; mi < 4; mi++)
#pragma unroll
                for (int n8 = 0; n8 < 8; n8++)
                    mma16816(acc[mi][n8], af[mi], &bf[n8 >> 1][(n8 & 1) * 2]);
        }
        __syncthreads();           // readers done before next load overwrites
    }

    // Epilogue: +bias (and exact-erf GELU for EPI==1), direct vector stores
    int erow = tm * 128 + wm * 64 + (lane >> 2);
    int ecol = tn * 128 + wn * 64 + 2 * (lane & 3);
#pragma unroll
    for (int mi = 0; mi < 4; mi++) {
#pragma unroll
        for (int n8 = 0; n8 < 8; n8++) {
            int r = erow + mi * 16;
            int c = ecol + n8 * 8;
            float bv0 = __ldg(bias + c), bv1 = __ldg(bias + c + 1);
            float v0 = acc[mi][n8][0] + bv0, v1 = acc[mi][n8][1] + bv1;
            float v2 = acc[mi][n8][2] + bv0, v3 = acc[mi][n8][3] + bv1;
            if (EPI == 1) {
                const float is2 = 0.70710678118654752f;
                v0 = 0.5f * v0 * (1.0f + erff(v0 * is2));
                v1 = 0.5f * v1 * (1.0f + erff(v1 * is2));
                v2 = 0.5f * v2 * (1.0f + erff(v2 * is2));
                v3 = 0.5f * v3 * (1.0f + erff(v3 * is2));
                __half2* p0 = (__half2*)(g_hh + (size_t)r * N_ + c);
                __half2* p1 = (__half2*)(g_hh + (size_t)(r + 8) * N_ + c);
                *p0 = __floats2half2_rn(v0, v1);
                *p1 = __floats2half2_rn(v2, v3);
            } else {
                float2* p0 = (float2*)(outf + (size_t)r * N_ + c);
                float2* p1 = (float2*)(outf + (size_t)(r + 8) * N_ + c);
                *p0 = make_float2(v0, v1);
                *p1 = make_float2(v2, v3);
            }
        }
    }
}

// ---------------------------------------------------------------------------
extern "C" void kernel_launch(void* const* d_in, const int* in_sizes, int n_in,
                              void* d_out, int out_size) {
    (void)in_sizes; (void)n_in; (void)out_size;
    const float* x  = (const float*)d_in[0];
    const float* W1 = (const float*)d_in[1];
    const float* b1 = (const float*)d_in[2];
    const float* W2 = (const float*)d_in[3];
    const float* b2 = (const float*)d_in[4];
    float* out = (float*)d_out;

    cudaFuncSetAttribute(gemm_fp16<1>, cudaFuncAttributeMaxDynamicSharedMemorySize, SMEM_DYN);
    cudaFuncSetAttribute(gemm_fp16<2>, cudaFuncAttributeMaxDynamicSharedMemorySize, SMEM_DYN);

    // Launch indices: 0 reduce, 1 finalize, 2 prep_fused, 3 gemm1 (<- ncu), 4 gemm2
    reduce_abs2<<<2048, 256>>>((const float4*)W1, (const float4*)W2);
    finalize_scales<<<2, 1024>>>();
    prep_fused<<<16384, 256>>>((const float4*)W1, (const float4*)W2, (const float4*)x);
    gemm_fp16<1><<<(MTOK / 128) * (FF / 128), 128, SMEM_DYN>>>(b1, nullptr);
    gemm_fp16<2><<<(MTOK / 128) * (EMB / 128), 128, SMEM_DYN>>>(b2, out);
}